// round 7
// baseline (speedup 1.0000x reference)
#include <cuda_runtime.h>
#include <math.h>

// ---------------- static scratch ----------------
#define TOT_CH 1472
#define EXC_CAP (1 << 21)

__device__ unsigned int g_chmin[TOT_CH], g_chmax[TOT_CH];   // ordered-key float
__device__ int          g_cnt[TOT_CH][6];    // cnt_k = #(val >= T_k), k=1..5
__device__ int          g_cg[TOT_CH][6];     // exception gidx counts (g<5)
__device__ float        g_ptab[TOT_CH][6];
__device__ float        g_pborder[TOT_CH];
__device__ float        g_S5[5], g_Bc[5];    // interior / border proc constants
__device__ int          g_excCnt[5];
__device__ unsigned int g_exc[5 * EXC_CAP];  // packed: p[0:18) | c[18:27) | g[27:30)
__device__ float        g_delta[306900];     // proc deltas (exceptions only)
__device__ unsigned int g_procmin[5], g_procmax[5];
__device__ float        g_resized[5 * 57600];
__device__ unsigned int g_rmin[5], g_rmax[5];
__device__ float        g_rsum[5];

__device__ __forceinline__ unsigned fkey(float f) {
    unsigned u = __float_as_uint(f);
    return (u & 0x80000000u) ? ~u : (u | 0x80000000u);
}
__device__ __forceinline__ float funkey(unsigned u) {
    return (u & 0x80000000u) ? __uint_as_float(u & 0x7fffffffu) : __uint_as_float(~u);
}
__device__ __forceinline__ float wrMin(float v) {
    #pragma unroll
    for (int o = 16; o; o >>= 1) v = fminf(v, __shfl_xor_sync(0xffffffffu, v, o));
    return v;
}
__device__ __forceinline__ float wrMax(float v) {
    #pragma unroll
    for (int o = 16; o; o >>= 1) v = fmaxf(v, __shfl_xor_sync(0xffffffffu, v, o));
    return v;
}
__device__ __forceinline__ float wrSum(float v) {
    #pragma unroll
    for (int o = 16; o; o >>= 1) v += __shfl_xor_sync(0xffffffffu, v, o);
    return v;
}
__device__ __forceinline__ int wrSumI(int v) {
    #pragma unroll
    for (int o = 16; o; o >>= 1) v += __shfl_xor_sync(0xffffffffu, v, o);
    return v;
}
__device__ void blockMinMax(float& mn, float& mx) {
    __shared__ float smn[8], smx[8];
    int lane = threadIdx.x & 31, w = threadIdx.x >> 5;
    mn = wrMin(mn); mx = wrMax(mx);
    if (lane == 0) { smn[w] = mn; smx[w] = mx; }
    __syncthreads();
    if (threadIdx.x < 8) { mn = smn[threadIdx.x]; mx = smx[threadIdx.x]; }
    else { mn = INFINITY; mx = -INFINITY; }
    if (w == 0) { mn = wrMin(mn); mx = wrMax(mx); }
}
__device__ void blockMinMaxSum(float& mn, float& mx, float& sm) {
    __shared__ float smn[8], smx[8], ssm[8];
    int lane = threadIdx.x & 31, w = threadIdx.x >> 5;
    mn = wrMin(mn); mx = wrMax(mx); sm = wrSum(sm);
    if (lane == 0) { smn[w] = mn; smx[w] = mx; ssm[w] = sm; }
    __syncthreads();
    if (threadIdx.x < 8) { mn = smn[threadIdx.x]; mx = smx[threadIdx.x]; sm = ssm[threadIdx.x]; }
    else { mn = INFINITY; mx = -INFINITY; sm = 0.f; }
    if (w == 0) { mn = wrMin(mn); mx = wrMax(mx); sm = wrSum(sm); }
}

// ---------------- kernels ----------------

__global__ void k_init() {
    int i = blockIdx.x * blockDim.x + threadIdx.x;
    if (i < TOT_CH) { g_chmin[i] = 0xFFFFFFFFu; g_chmax[i] = 0u; }
    if (i < TOT_CH * 6) { ((int*)g_cnt)[i] = 0; ((int*)g_cg)[i] = 0; }
    if (i < 306900) g_delta[i] = 0.f;
    if (i < 5) {
        g_excCnt[i] = 0; g_S5[i] = 0.f; g_Bc[i] = 0.f;
        g_procmin[i] = 0xFFFFFFFFu; g_procmax[i] = 0u;
        g_rmin[i] = 0xFFFFFFFFu; g_rmax[i] = 0u; g_rsum[i] = 0.f;
    }
}

// ---- fused min/max pass ----
template <int W, int H, int VEC>
__device__ __forceinline__ void minmax_body(const float* __restrict__ in,
                                            int chanBase, int widx, int splits) {
    constexpr int Wc = W / VEC;
    constexpr int Nc = (H - 2) * Wc;
    int c = widx / splits;
    int sp = widx - c * splits;
    const float* ch = in + (size_t)c * H * W;
    int chunk = (Nc + splits - 1) / splits;
    int lo = sp * chunk, hi = min(Nc, lo + chunk);
    float mn0 = 0.f, mx0 = 0.f, mn1 = 0.f, mx1 = 0.f;  // include border zeros
    #pragma unroll 2
    for (int i = lo + threadIdx.x; i < hi; i += 256) {
        int q = i / Wc;
        int xc = i - q * Wc;
        const float* pv = ch + (q + 1) * W + xc * VEC;
        float v[VEC];
        if (VEC == 4) {
            float4 t = *(const float4*)pv;
            v[0] = t.x; v[1] = t.y; v[2] = t.z; v[3] = t.w;
        } else {
            float2 t = *(const float2*)pv;
            v[0] = t.x; v[1] = t.y;
        }
        if (xc == 0) v[0] = 0.f;
        if (xc == Wc - 1) v[VEC - 1] = 0.f;
        #pragma unroll
        for (int s = 0; s < VEC; s += 2) { mn0 = fminf(mn0, v[s]); mx0 = fmaxf(mx0, v[s]); }
        #pragma unroll
        for (int s = 1; s < VEC; s += 2) { mn1 = fminf(mn1, v[s]); mx1 = fmaxf(mx1, v[s]); }
    }
    float vmn = fminf(mn0, mn1), vmx = fmaxf(mx0, mx1);
    blockMinMax(vmn, vmx);
    if (threadIdx.x == 0) {
        atomicMin(&g_chmin[chanBase + c], fkey(vmn));
        atomicMax(&g_chmax[chanBase + c], fkey(vmx));
    }
}

__global__ void __launch_bounds__(256) k_minmaxAll(
    const float* __restrict__ l0, const float* __restrict__ l1,
    const float* __restrict__ l2, const float* __restrict__ l3,
    const float* __restrict__ l4) {
    int b = blockIdx.x;
    if (b < 1024)      minmax_body<480, 480, 4>(l0, 0,   b,        16);
    else if (b < 1536) minmax_body<240, 240, 4>(l1, 64,  b - 1024, 4);
    else if (b < 1792) minmax_body<120, 120, 4>(l2, 192, b - 1536, 1);
    else if (b < 2304) minmax_body< 60,  60, 4>(l3, 448, b - 1792, 1);
    else               minmax_body< 30,  30, 2>(l4, 960, b - 2304, 1);
}

// ---- fused histogram pass ----
// NOTE: loop trip count is block-uniform (iters) so every thread participates
// in every warp collective; out-of-range lanes carry the -1 sentinel.
template <int W, int H, int VEC>
__device__ __forceinline__ void hist_body(const float* __restrict__ in,
                                          int chanBase, int layer,
                                          int widx, int splits) {
    constexpr int Wc = W / VEC;
    constexpr int Nc = (H - 2) * Wc;
    int c = widx / splits;
    int sp = widx - c * splits;
    int gch = chanBase + c;
    const float* ch = in + (size_t)c * H * W;
    float mn = funkey(g_chmin[gch]);
    float mx = funkey(g_chmax[gch]);
    float rng = mx - mn;
    if (rng == 0.f) return;  // degenerate channel handled in tables (block-uniform exit)
    float T1 = mn + rng * (1.f / 6.f), T2 = mn + rng * (2.f / 6.f),
          T3 = mn + rng * (3.f / 6.f), T4 = mn + rng * (4.f / 6.f),
          T5 = mn + rng * (5.f / 6.f);
    float Texc = mn + rng * (1.5f / 256.f);  // widened g<5 candidate band

    int c1 = 0, c2 = 0, c3 = 0, c4 = 0, c5 = 0;
    int chunk = (Nc + splits - 1) / splits;
    int lo = sp * chunk, hi = min(Nc, lo + chunk);
    int span = hi - lo;
    int iters = (span + 255) / 256;          // block-uniform trip count
    int lane = threadIdx.x & 31;

    for (int t = 0; t < iters; t++) {
        int i = lo + t * 256 + threadIdx.x;
        bool inR = i < hi;
        float v[VEC];
        if (inR) {
            int q = i / Wc;
            int xc = i - q * Wc;
            const float* pv = ch + (q + 1) * W + xc * VEC;
            if (VEC == 4) {
                float4 tv = *(const float4*)pv;
                v[0] = tv.x; v[1] = tv.y; v[2] = tv.z; v[3] = tv.w;
            } else {
                float2 tv = *(const float2*)pv;
                v[0] = tv.x; v[1] = tv.y;
            }
            if (xc == 0) v[0] = -1.f;           // x-border: excluded (analytic)
            if (xc == Wc - 1) v[VEC - 1] = -1.f;
        } else {
            #pragma unroll
            for (int s = 0; s < VEC; s++) v[s] = -1.f;
        }
        bool anyE = false;
        bool e[VEC];
        #pragma unroll
        for (int s = 0; s < VEC; s++) {
            float val = v[s];
            c1 += (val >= T1); c2 += (val >= T2); c3 += (val >= T3);
            c4 += (val >= T4); c5 += (val >= T5);
            e[s] = (val >= 0.f) && (val < Texc);
            anyE = anyE || e[s];
        }
        // warp-aggregated exception append (rare); all 32 lanes present here
        if (__any_sync(0xffffffffu, anyE)) {
            #pragma unroll
            for (int s = 0; s < VEC; s++) {
                int g = 5;
                if (e[s]) {
                    // exact jnp arithmetic for the rare path
                    float vn = __fmul_rn(__fdiv_rn(__fsub_rn(v[s], mn), rng), 256.0f);
                    g = (int)truncf(__fsub_rn(__fmul_rn(vn, 6.0f), 1.0f));
                    g = max(0, min(5, g));
                }
                bool push = e[s] && (g < 5);
                unsigned m2 = __ballot_sync(0xffffffffu, push);
                if (m2) {
                    int leader = __ffs(m2) - 1;
                    int cnt = __popc(m2);
                    int base = 0;
                    if (lane == leader) base = atomicAdd(&g_excCnt[layer], cnt);
                    base = __shfl_sync(0xffffffffu, base, leader);
                    if (push) {
                        int rank = __popc(m2 & ((1u << lane) - 1u));
                        int idx = base + rank;
                        atomicAdd(&g_cg[gch][g], 1);
                        if (idx < EXC_CAP) {
                            int q = i / Wc;
                            int xc = i - q * Wc;
                            int p = (q + 1) * W + xc * VEC + s;
                            g_exc[layer * EXC_CAP + idx] =
                                (unsigned)p | ((unsigned)c << 18) | ((unsigned)g << 27);
                        }
                    }
                }
            }
        }
    }
    c1 = wrSumI(c1); c2 = wrSumI(c2); c3 = wrSumI(c3);
    c4 = wrSumI(c4); c5 = wrSumI(c5);
    if (lane == 0) {
        atomicAdd(&g_cnt[gch][1], c1); atomicAdd(&g_cnt[gch][2], c2);
        atomicAdd(&g_cnt[gch][3], c3); atomicAdd(&g_cnt[gch][4], c4);
        atomicAdd(&g_cnt[gch][5], c5);
    }
}

__global__ void __launch_bounds__(256) k_histAll(
    const float* __restrict__ l0, const float* __restrict__ l1,
    const float* __restrict__ l2, const float* __restrict__ l3,
    const float* __restrict__ l4) {
    int b = blockIdx.x;
    if (b < 1024)      hist_body<480, 480, 4>(l0, 0,   0, b,        16);
    else if (b < 1536) hist_body<240, 240, 4>(l1, 64,  1, b - 1024, 4);
    else if (b < 1792) hist_body<120, 120, 4>(l2, 192, 2, b - 1536, 1);
    else if (b < 2304) hist_body< 60,  60, 4>(l3, 448, 3, b - 1792, 1);
    else               hist_body< 30,  30, 2>(l4, 960, 4, b - 2304, 1);
}

// per-channel table math (border pixels: bin0 / gidx0, handled analytically)
__global__ void __launch_bounds__(256) k_tables() {
    __shared__ float sS5[5], sBc[5];
    if (threadIdx.x < 5) { sS5[threadIdx.x] = 0.f; sBc[threadIdx.x] = 0.f; }
    __syncthreads();

    int ch = blockIdx.x * blockDim.x + threadIdx.x;
    const int cbnd[6] = {0, 64, 192, 448, 960, 1472};
    const int Hs[5] = {480, 240, 120, 60, 30};
    int layer = 0;
    if (ch < TOT_CH) {
        #pragma unroll
        for (int l = 1; l < 5; l++) if (ch >= cbnd[l]) layer = l;
        int cIn = ch - cbnd[layer];
        int H = Hs[layer], HW = H * H, nb = 4 * H - 4, Nin = (H - 2) * (H - 2);

        float mn = funkey(g_chmin[ch]), mx = funkey(g_chmax[ch]);
        float ptab[6] = {0, 0, 0, 0, 0, 0};
        float pb = 0.f;

        if (mx - mn != 0.f) {
            int n1 = g_cnt[ch][1], n2 = g_cnt[ch][2], n3 = g_cnt[ch][3],
                n4 = g_cnt[ch][4], n5 = g_cnt[ch][5];
            int cb[6];
            cb[0] = Nin - n1 + nb; cb[1] = n1 - n2; cb[2] = n2 - n3;
            cb[3] = n3 - n4; cb[4] = n4 - n5; cb[5] = n5;
            int cg[6]; int sumE = 0;
            #pragma unroll
            for (int g = 0; g < 5; g++) { cg[g] = g_cg[ch][g]; sumE += cg[g]; }
            cg[5] = Nin - sumE;
            cg[0] += nb;  // border pixels: gidx 0

            float hv[6];
            #pragma unroll
            for (int b = 0; b < 6; b++)
                hv[b] = -__logf((float)cb[b] / (float)HW + 1e-4f);

            float dmn = INFINITY, dmx = -INFINITY;
            #pragma unroll
            for (int g = 0; g < 6; g++) if (cg[g] > 0) { dmn = fminf(dmn, hv[g]); dmx = fmaxf(dmx, hv[g]); }
            float drng = dmx - dmn;
            float dst[6];
            #pragma unroll
            for (int g = 0; g < 6; g++) dst[g] = (drng == 0.f) ? 0.f : (hv[g] - dmn) / drng;
            float meanD = 0.f;
            #pragma unroll
            for (int g = 0; g < 6; g++) meanD += (float)cg[g] * dst[g];
            meanD /= (float)HW;
            float maxD = -INFINITY;
            #pragma unroll
            for (int g = 0; g < 6; g++) if (cg[g] > 0) maxD = fmaxf(maxD, dst[g]);
            float wr = (maxD - meanD); wr *= wr;
            float rt[6];
            #pragma unroll
            for (int g = 0; g < 6; g++) rt[g] = dst[g] * wr;

            // maps stats: c==0 keeps border (value rt[0]); c>=1 border zeroed
            float mmn, mmx, msum = 0.f;
            if (cIn == 0) {
                mmn = INFINITY; mmx = -INFINITY;
                #pragma unroll
                for (int g = 0; g < 6; g++) if (cg[g] > 0) {
                    mmn = fminf(mmn, rt[g]); mmx = fmaxf(mmx, rt[g]);
                    msum += (float)cg[g] * rt[g];
                }
            } else {
                mmn = 0.f; mmx = 0.f;
                #pragma unroll
                for (int g = 0; g < 6; g++) {
                    int ci = cg[g] - ((g == 0) ? nb : 0);
                    if (ci > 0) { mmn = fminf(mmn, rt[g]); mmx = fmaxf(mmx, rt[g]); msum += (float)ci * rt[g]; }
                }
            }
            float mrng = mmx - mmn;
            float wp = mmx - msum / (float)HW; wp *= wp;
            #pragma unroll
            for (int g = 0; g < 6; g++)
                ptab[g] = (mrng == 0.f) ? 0.f : ((rt[g] - mmn) / mrng) * wp;
            pb = (cIn == 0) ? 0.f : ((mrng == 0.f) ? 0.f : ((0.f - mmn) / mrng) * wp);
        }
        #pragma unroll
        for (int g = 0; g < 6; g++) g_ptab[ch][g] = ptab[g];
        g_pborder[ch] = pb;
        atomicAdd(&sS5[layer], ptab[5]);
        atomicAdd(&sBc[layer], (cIn == 0) ? ptab[0] : pb);
    }
    __syncthreads();
    if (threadIdx.x < 5) {
        if (sS5[threadIdx.x] != 0.f) atomicAdd(&g_S5[threadIdx.x], sS5[threadIdx.x]);
        if (sBc[threadIdx.x] != 0.f) atomicAdd(&g_Bc[threadIdx.x], sBc[threadIdx.x]);
    }
}

__global__ void k_scatter() {
    const int pOff[5] = {0, 230400, 288000, 302400, 306000};
    const int cbnd[5] = {0, 64, 192, 448, 960};
    int tid = blockIdx.x * blockDim.x + threadIdx.x;
    int stride = gridDim.x * blockDim.x;
    for (int l = 0; l < 5; l++) {
        int n = min(g_excCnt[l], EXC_CAP);
        for (int j = tid; j < n; j += stride) {
            unsigned e = g_exc[l * EXC_CAP + j];
            int p = e & 0x3FFFF;
            int c = (e >> 18) & 0x1FF;
            int g = (e >> 27) & 7;
            float d = g_ptab[cbnd[l] + c][g] - g_ptab[cbnd[l] + c][5];
            atomicAdd(&g_delta[pOff[l] + p], d);
        }
    }
}

__global__ void k_procstats() {
    // fused block ranges: l0:900, l1:225, l2:57, l3:15, l4:4
    const int pOff[5] = {0, 230400, 288000, 302400, 306000};
    const int HWs[5] = {230400, 57600, 14400, 3600, 900};
    const int Ws[5] = {480, 240, 120, 60, 30};
    const int bLo[6] = {0, 900, 1125, 1182, 1197, 1201};
    int b = blockIdx.x;
    int layer = 0;
    #pragma unroll
    for (int l = 1; l < 5; l++) if (b >= bLo[l]) layer = l;
    int i = (b - bLo[layer]) * blockDim.x + threadIdx.x;
    float mn = INFINITY, mx = -INFINITY;
    if (i < HWs[layer]) {
        int W = Ws[layer];
        int y = i / W, x = i - y * W;
        bool border = (y == 0 || x == 0 || y == W - 1 || x == W - 1);
        float v = border ? g_Bc[layer] : (g_S5[layer] + g_delta[pOff[layer] + i]);
        mn = v; mx = v;
    }
    blockMinMax(mn, mx);
    if (threadIdx.x == 0) {
        atomicMin(&g_procmin[layer], fkey(mn));
        atomicMax(&g_procmax[layer], fkey(mx));
    }
}

// jax.image.resize (linear, antialias) of thresholded normalized proc -> 240x240
__global__ void k_resize() {
    const int pOff[5] = {0, 230400, 288000, 302400, 306000};
    const int Hs[5] = {480, 240, 120, 60, 30};
    int layer = blockIdx.y;
    int H = Hs[layer], W = H;
    int o = blockIdx.x * blockDim.x + threadIdx.x;  // 0..57599
    float pmn = funkey(g_procmin[layer]);
    float pmx = funkey(g_procmax[layer]);
    float prng = pmx - pmn;
    float S5 = g_S5[layer], Bc = g_Bc[layer];
    int oy = o / 240, ox = o - oy * 240;
    float inv = (float)H / 240.0f;
    float ks = fmaxf(inv, 1.0f);
    float fy = ((float)oy + 0.5f) * inv - 0.5f;
    float fx = ((float)ox + 0.5f) * inv - 0.5f;
    int ylo = max(0, (int)ceilf(fy - ks)), yhi = min(H - 1, (int)floorf(fy + ks));
    int xlo = max(0, (int)ceilf(fx - ks)), xhi = min(W - 1, (int)floorf(fx + ks));
    float wx[8]; float wxs = 0.f;
    for (int j = xlo; j <= xhi; j++) {
        float w = fmaxf(0.f, 1.0f - fabsf(fx - (float)j) / ks);
        wx[j - xlo] = w; wxs += w;
    }
    const float* dl = g_delta + pOff[layer];
    float acc = 0.f, wys = 0.f;
    for (int j = ylo; j <= yhi; j++) {
        float wy = fmaxf(0.f, 1.0f - fabsf(fy - (float)j) / ks);
        wys += wy;
        if (wy != 0.f) {
            bool rowB = (j == 0 || j == H - 1);
            float rowacc = 0.f;
            for (int i = xlo; i <= xhi; i++) {
                bool border = rowB || i == 0 || i == W - 1;
                float v = border ? Bc : (S5 + dl[j * W + i]);
                float n = (prng == 0.f) ? 0.f : (v - pmn) / prng;
                if (n < 0.2f) n = 0.f;
                rowacc += wx[i - xlo] * n;
            }
            acc += wy * rowacc;
        }
    }
    float val = acc / (wys * wxs);
    g_resized[layer * 57600 + o] = val;
    float mn = val, mx = val, sm = val;
    blockMinMaxSum(mn, mx, sm);
    if (threadIdx.x == 0) {
        atomicMin(&g_rmin[layer], fkey(mn));
        atomicMax(&g_rmax[layer], fkey(mx));
        atomicAdd(&g_rsum[layer], sm);
    }
}

__global__ void k_final(float* __restrict__ out, int out_size) {
    int o = blockIdx.x * blockDim.x + threadIdx.x;
    float s = 0.f;
    float grp[5];
    #pragma unroll
    for (int l = 0; l < 5; l++) {
        float rmn = funkey(g_rmin[l]), rmx = funkey(g_rmax[l]);
        float rng = rmx - rmn;
        float mean = g_rsum[l] / 57600.0f;
        float w = (rmx - mean); w *= w;
        float v = g_resized[l * 57600 + o];
        float n = (rng == 0.f) ? 0.f : (v - rmn) / rng;
        float g = (w == 0.f || rng == 0.f) ? 0.f : (n * w / w * 256.0f);
        grp[l] = g;
        s += g;
    }
    out[o] = s;
    if (out_size >= 345600) {
        float* og = out + 57600;
        #pragma unroll
        for (int l = 0; l < 5; l++) og[o * 5 + l] = grp[l];
    }
}

// ---------------- launch ----------------
extern "C" void kernel_launch(void* const* d_in, const int* in_sizes, int n_in,
                              void* d_out, int out_size) {
    const float* l0 = (const float*)d_in[0];
    const float* l1 = (const float*)d_in[1];
    const float* l2 = (const float*)d_in[2];
    const float* l3 = (const float*)d_in[3];
    const float* l4 = (const float*)d_in[4];

    k_init<<<(306900 + 255) / 256, 256>>>();
    k_minmaxAll<<<2816, 256>>>(l0, l1, l2, l3, l4);
    k_histAll<<<2816, 256>>>(l0, l1, l2, l3, l4);
    k_tables<<<6, 256>>>();
    k_scatter<<<256, 256>>>();
    k_procstats<<<1201, 256>>>();
    k_resize<<<dim3(225, 5), 256>>>();
    k_final<<<225, 256>>>((float*)d_out, out_size);
}

// round 9
// speedup vs baseline: 1.0146x; 1.0146x over previous
#include <cuda_runtime.h>
#include <cooperative_groups.h>
#include <math.h>
namespace cg = cooperative_groups;

// ---------------- static scratch ----------------
#define TOT_CH 1472
#define EXC_CAP (1 << 21)
#define NB 592
#define NTH (NB * 256)

__device__ float        g_partMn[TOT_CH * 16], g_partMx[TOT_CH * 16];  // per-(ch,split) min/max
__device__ int          g_cntPart[TOT_CH * 16 * 5];  // per-(ch,split) threshold counts
__device__ int          g_cg[TOT_CH][6];     // exception gidx counts (g<5) [atomic, rare]
__device__ float        g_ptab[TOT_CH][6];
__device__ float        g_S5[5], g_Bc[5];    // interior / border proc constants
__device__ int          g_excCnt[5];
__device__ unsigned int g_exc[5 * EXC_CAP];  // packed: p[0:18) | c[18:27) | g[27:30)
__device__ float        g_delta[306900];     // proc deltas (exceptions only)
__device__ unsigned int g_procmin[5], g_procmax[5];
__device__ float        g_resized[5 * 57600];
__device__ unsigned int g_rmin[5], g_rmax[5];
__device__ float        g_rsum[5];
__device__ volatile unsigned g_barCount;

__device__ __forceinline__ unsigned fkey(float f) {
    unsigned u = __float_as_uint(f);
    return (u & 0x80000000u) ? ~u : (u | 0x80000000u);
}
__device__ __forceinline__ float funkey(unsigned u) {
    return (u & 0x80000000u) ? __uint_as_float(u & 0x7fffffffu) : __uint_as_float(~u);
}
__device__ __forceinline__ float wrMin(float v) {
    #pragma unroll
    for (int o = 16; o; o >>= 1) v = fminf(v, __shfl_xor_sync(0xffffffffu, v, o));
    return v;
}
__device__ __forceinline__ float wrMax(float v) {
    #pragma unroll
    for (int o = 16; o; o >>= 1) v = fmaxf(v, __shfl_xor_sync(0xffffffffu, v, o));
    return v;
}
__device__ __forceinline__ float wrSum(float v) {
    #pragma unroll
    for (int o = 16; o; o >>= 1) v += __shfl_xor_sync(0xffffffffu, v, o);
    return v;
}
__device__ __forceinline__ int wrSumI(int v) {
    #pragma unroll
    for (int o = 16; o; o >>= 1) v += __shfl_xor_sync(0xffffffffu, v, o);
    return v;
}
__device__ void blockMinMax(float& mn, float& mx) {
    __shared__ float smn[8], smx[8];
    int lane = threadIdx.x & 31, w = threadIdx.x >> 5;
    mn = wrMin(mn); mx = wrMax(mx);
    if (lane == 0) { smn[w] = mn; smx[w] = mx; }
    __syncthreads();
    if (threadIdx.x < 8) { mn = smn[threadIdx.x]; mx = smx[threadIdx.x]; }
    else { mn = INFINITY; mx = -INFINITY; }
    if (w == 0) { mn = wrMin(mn); mx = wrMax(mx); }
    __syncthreads();
}

// cumulative-count grid barrier (no reset -> no reuse race). g_barCount zeroed
// in k_minmaxAll; target is NB * barrier_index.
__device__ __forceinline__ void gridBar(unsigned target) {
    __threadfence();
    __syncthreads();
    if (threadIdx.x == 0) {
        atomicAdd((unsigned*)&g_barCount, 1u);
        while (g_barCount < target) __nanosleep(64);
        __threadfence();
    }
    __syncthreads();
}

// ---------------- kernel 1: init + per-(ch,split) min/max partials ----------------
template <int W, int H, int VEC>
__device__ __forceinline__ void minmax_body(const float* __restrict__ in,
                                            int chanBase, int widx, int splits) {
    constexpr int Wc = W / VEC;
    constexpr int Nc = (H - 2) * Wc;
    int c = widx / splits;
    int sp = widx - c * splits;
    const float* ch = in + (size_t)c * H * W;
    int chunk = (Nc + splits - 1) / splits;
    int lo = sp * chunk, hi = min(Nc, lo + chunk);
    float mn0 = 0.f, mx0 = 0.f, mn1 = 0.f, mx1 = 0.f;  // include border zeros
    #pragma unroll 2
    for (int i = lo + threadIdx.x; i < hi; i += 256) {
        int q = i / Wc;
        int xc = i - q * Wc;
        const float* pv = ch + (q + 1) * W + xc * VEC;
        float v[VEC];
        if (VEC == 4) {
            float4 t = *(const float4*)pv;
            v[0] = t.x; v[1] = t.y; v[2] = t.z; v[3] = t.w;
        } else {
            float2 t = *(const float2*)pv;
            v[0] = t.x; v[1] = t.y;
        }
        if (xc == 0) v[0] = 0.f;
        if (xc == Wc - 1) v[VEC - 1] = 0.f;
        #pragma unroll
        for (int s = 0; s < VEC; s += 2) { mn0 = fminf(mn0, v[s]); mx0 = fmaxf(mx0, v[s]); }
        #pragma unroll
        for (int s = 1; s < VEC; s += 2) { mn1 = fminf(mn1, v[s]); mx1 = fmaxf(mx1, v[s]); }
    }
    float vmn = fminf(mn0, mn1), vmx = fmaxf(mx0, mx1);
    blockMinMax(vmn, vmx);
    if (threadIdx.x == 0) {
        g_partMn[(chanBase + c) * 16 + sp] = vmn;   // plain store, no init needed
        g_partMx[(chanBase + c) * 16 + sp] = vmx;
    }
}

__global__ void __launch_bounds__(256) k_minmaxAll(
    const float* __restrict__ l0, const float* __restrict__ l1,
    const float* __restrict__ l2, const float* __restrict__ l3,
    const float* __restrict__ l4) {
    // fold all small inits into this kernel (consumed only by LATER kernels)
    int gt = blockIdx.x * 256 + threadIdx.x;
    if (gt < 306900) g_delta[gt] = 0.f;
    if (gt < TOT_CH * 6) ((int*)g_cg)[gt] = 0;
    if (gt < 5) {
        g_excCnt[gt] = 0; g_S5[gt] = 0.f; g_Bc[gt] = 0.f;
        g_procmin[gt] = 0xFFFFFFFFu; g_procmax[gt] = 0u;
        g_rmin[gt] = 0xFFFFFFFFu; g_rmax[gt] = 0u; g_rsum[gt] = 0.f;
    }
    if (gt == 7) g_barCount = 0u;

    int b = blockIdx.x;
    if (b < 1024)      minmax_body<480, 480, 4>(l0, 0,   b,        16);
    else if (b < 1536) minmax_body<240, 240, 4>(l1, 64,  b - 1024, 4);
    else if (b < 1792) minmax_body<120, 120, 4>(l2, 192, b - 1536, 1);
    else if (b < 2304) minmax_body< 60,  60, 4>(l3, 448, b - 1792, 1);
    else               minmax_body< 30,  30, 2>(l4, 960, b - 2304, 1);
}

// ---------------- kernel 2: histogram partials + exceptions ----------------
template <int W, int H, int VEC>
__device__ __forceinline__ void hist_body(const float* __restrict__ in,
                                          int chanBase, int layer,
                                          int widx, int splits) {
    constexpr int Wc = W / VEC;
    constexpr int Nc = (H - 2) * Wc;
    int c = widx / splits;
    int sp = widx - c * splits;
    int gch = chanBase + c;
    const float* ch = in + (size_t)c * H * W;
    // reduce min/max from partials (block-uniform, L1-hot)
    float mn = INFINITY, mx = -INFINITY;
    for (int s = 0; s < splits; s++) {
        mn = fminf(mn, g_partMn[gch * 16 + s]);
        mx = fmaxf(mx, g_partMx[gch * 16 + s]);
    }
    float rng = mx - mn;
    if (rng == 0.f) return;  // degenerate: tables ignores counts (block-uniform exit)
    float T1 = mn + rng * (1.f / 6.f), T2 = mn + rng * (2.f / 6.f),
          T3 = mn + rng * (3.f / 6.f), T4 = mn + rng * (4.f / 6.f),
          T5 = mn + rng * (5.f / 6.f);
    float Texc = mn + rng * (1.5f / 256.f);  // widened g<5 candidate band

    int c1 = 0, c2 = 0, c3 = 0, c4 = 0, c5 = 0;
    int chunk = (Nc + splits - 1) / splits;
    int lo = sp * chunk, hi = min(Nc, lo + chunk);

    for (int i = lo + threadIdx.x; i < hi; i += 256) {
        int q = i / Wc;
        int xc = i - q * Wc;
        const float* pv = ch + (q + 1) * W + xc * VEC;
        float v[VEC];
        if (VEC == 4) {
            float4 tv = *(const float4*)pv;
            v[0] = tv.x; v[1] = tv.y; v[2] = tv.z; v[3] = tv.w;
        } else {
            float2 tv = *(const float2*)pv;
            v[0] = tv.x; v[1] = tv.y;
        }
        if (xc == 0) v[0] = -1.f;           // x-border: excluded (analytic)
        if (xc == Wc - 1) v[VEC - 1] = -1.f;
        #pragma unroll
        for (int s = 0; s < VEC; s++) {
            float val = v[s];
            c1 += (val >= T1); c2 += (val >= T2); c3 += (val >= T3);
            c4 += (val >= T4); c5 += (val >= T5);
            if (val >= 0.f && val < Texc) {   // rare
                // exact jnp arithmetic for the rare path
                float vn = __fmul_rn(__fdiv_rn(__fsub_rn(val, mn), rng), 256.0f);
                int g = (int)truncf(__fsub_rn(__fmul_rn(vn, 6.0f), 1.0f));
                g = max(0, min(5, g));
                if (g < 5) {
                    // coalesced-group aggregated append (safe under divergence)
                    cg::coalesced_group grp = cg::coalesced_threads();
                    int base = 0;
                    if (grp.thread_rank() == 0)
                        base = atomicAdd(&g_excCnt[layer], (int)grp.size());
                    base = grp.shfl(base, 0);
                    int idx = base + (int)grp.thread_rank();
                    atomicAdd(&g_cg[gch][g], 1);
                    if (idx < EXC_CAP) {
                        int p = (q + 1) * W + xc * VEC + s;
                        g_exc[layer * EXC_CAP + idx] =
                            (unsigned)p | ((unsigned)c << 18) | ((unsigned)g << 27);
                    }
                }
            }
        }
    }
    // block-reduce counts, plain store per (ch,split)
    __shared__ int sc[5];
    if (threadIdx.x < 5) sc[threadIdx.x] = 0;
    __syncthreads();
    c1 = wrSumI(c1); c2 = wrSumI(c2); c3 = wrSumI(c3);
    c4 = wrSumI(c4); c5 = wrSumI(c5);
    if ((threadIdx.x & 31) == 0) {
        atomicAdd(&sc[0], c1); atomicAdd(&sc[1], c2); atomicAdd(&sc[2], c3);
        atomicAdd(&sc[3], c4); atomicAdd(&sc[4], c5);
    }
    __syncthreads();
    if (threadIdx.x == 0) {
        int* dst = &g_cntPart[(gch * 16 + sp) * 5];
        dst[0] = sc[0]; dst[1] = sc[1]; dst[2] = sc[2]; dst[3] = sc[3]; dst[4] = sc[4];
    }
}

__global__ void __launch_bounds__(256) k_histAll(
    const float* __restrict__ l0, const float* __restrict__ l1,
    const float* __restrict__ l2, const float* __restrict__ l3,
    const float* __restrict__ l4) {
    int b = blockIdx.x;
    if (b < 1024)      hist_body<480, 480, 4>(l0, 0,   0, b,        16);
    else if (b < 1536) hist_body<240, 240, 4>(l1, 64,  1, b - 1024, 4);
    else if (b < 1792) hist_body<120, 120, 4>(l2, 192, 2, b - 1536, 1);
    else if (b < 2304) hist_body< 60,  60, 4>(l3, 448, 3, b - 1792, 1);
    else               hist_body< 30,  30, 2>(l4, 960, 4, b - 2304, 1);
}

// ---------------- kernel 3: persistent tail (tables -> scatter -> stats -> resize -> final) ----------------
__global__ void __launch_bounds__(256, 4) k_tail(float* __restrict__ out, int out_size) {
    const int cbnd[6] = {0, 64, 192, 448, 960, 1472};
    const int Hs[5]  = {480, 240, 120, 60, 30};
    const int spl[5] = {16, 4, 1, 1, 1};
    const int pOff[5] = {0, 230400, 288000, 302400, 306000};
    const int HWs[5] = {230400, 57600, 14400, 3600, 900};
    int tid = threadIdx.x;
    int gt = blockIdx.x * 256 + tid;
    int lane = tid & 31;

    // ---- phase 1: tables (one channel per warp) ----
    {
        __shared__ float sS5[5], sBc[5];
        if (tid < 5) { sS5[tid] = 0.f; sBc[tid] = 0.f; }
        __syncthreads();
        int ch = gt >> 5;
        if (ch < TOT_CH) {
            int layer = 0;
            #pragma unroll
            for (int l = 1; l < 5; l++) if (ch >= cbnd[l]) layer = l;
            int cIn = ch - cbnd[layer];
            int splits = spl[layer];
            int H = Hs[layer], HW = H * H, nb = 4 * H - 4, Nin = (H - 2) * (H - 2);
            // warp-parallel partial reduction
            float mn = (lane < splits) ? g_partMn[ch * 16 + lane] : INFINITY;
            float mx = (lane < splits) ? g_partMx[ch * 16 + lane] : -INFINITY;
            mn = wrMin(mn); mx = wrMax(mx);
            int n1, n2, n3, n4, n5;
            {
                int v0 = (lane < splits) ? g_cntPart[(ch * 16 + lane) * 5 + 0] : 0;
                int v1 = (lane < splits) ? g_cntPart[(ch * 16 + lane) * 5 + 1] : 0;
                int v2 = (lane < splits) ? g_cntPart[(ch * 16 + lane) * 5 + 2] : 0;
                int v3 = (lane < splits) ? g_cntPart[(ch * 16 + lane) * 5 + 3] : 0;
                int v4 = (lane < splits) ? g_cntPart[(ch * 16 + lane) * 5 + 4] : 0;
                n1 = wrSumI(v0); n2 = wrSumI(v1); n3 = wrSumI(v2);
                n4 = wrSumI(v3); n5 = wrSumI(v4);
            }
            if (lane == 0) {
                float ptab[6] = {0, 0, 0, 0, 0, 0};
                float pb = 0.f;
                if (mx - mn != 0.f) {
                    int cb[6];
                    cb[0] = Nin - n1 + nb; cb[1] = n1 - n2; cb[2] = n2 - n3;
                    cb[3] = n3 - n4; cb[4] = n4 - n5; cb[5] = n5;
                    int cgc[6]; int sumE = 0;
                    #pragma unroll
                    for (int g = 0; g < 5; g++) { cgc[g] = g_cg[ch][g]; sumE += cgc[g]; }
                    cgc[5] = Nin - sumE;
                    cgc[0] += nb;  // border pixels: gidx 0
                    float hv[6];
                    #pragma unroll
                    for (int b2 = 0; b2 < 6; b2++)
                        hv[b2] = -__logf((float)cb[b2] / (float)HW + 1e-4f);
                    float dmn = INFINITY, dmx = -INFINITY;
                    #pragma unroll
                    for (int g = 0; g < 6; g++) if (cgc[g] > 0) { dmn = fminf(dmn, hv[g]); dmx = fmaxf(dmx, hv[g]); }
                    float drng = dmx - dmn;
                    float dst[6];
                    #pragma unroll
                    for (int g = 0; g < 6; g++) dst[g] = (drng == 0.f) ? 0.f : (hv[g] - dmn) / drng;
                    float meanD = 0.f;
                    #pragma unroll
                    for (int g = 0; g < 6; g++) meanD += (float)cgc[g] * dst[g];
                    meanD /= (float)HW;
                    float maxD = -INFINITY;
                    #pragma unroll
                    for (int g = 0; g < 6; g++) if (cgc[g] > 0) maxD = fmaxf(maxD, dst[g]);
                    float wr = (maxD - meanD); wr *= wr;
                    float rt[6];
                    #pragma unroll
                    for (int g = 0; g < 6; g++) rt[g] = dst[g] * wr;
                    float mmn, mmx, msum = 0.f;
                    if (cIn == 0) {
                        mmn = INFINITY; mmx = -INFINITY;
                        #pragma unroll
                        for (int g = 0; g < 6; g++) if (cgc[g] > 0) {
                            mmn = fminf(mmn, rt[g]); mmx = fmaxf(mmx, rt[g]);
                            msum += (float)cgc[g] * rt[g];
                        }
                    } else {
                        mmn = 0.f; mmx = 0.f;
                        #pragma unroll
                        for (int g = 0; g < 6; g++) {
                            int ci = cgc[g] - ((g == 0) ? nb : 0);
                            if (ci > 0) { mmn = fminf(mmn, rt[g]); mmx = fmaxf(mmx, rt[g]); msum += (float)ci * rt[g]; }
                        }
                    }
                    float mrng = mmx - mmn;
                    float wp = mmx - msum / (float)HW; wp *= wp;
                    #pragma unroll
                    for (int g = 0; g < 6; g++)
                        ptab[g] = (mrng == 0.f) ? 0.f : ((rt[g] - mmn) / mrng) * wp;
                    pb = (cIn == 0) ? 0.f : ((mrng == 0.f) ? 0.f : ((0.f - mmn) / mrng) * wp);
                }
                #pragma unroll
                for (int g = 0; g < 6; g++) g_ptab[ch][g] = ptab[g];
                atomicAdd(&sS5[layer], ptab[5]);
                atomicAdd(&sBc[layer], (cIn == 0) ? ptab[0] : pb);
            }
        }
        __syncthreads();
        if (tid < 5) {
            if (sS5[tid] != 0.f) atomicAdd(&g_S5[tid], sS5[tid]);
            if (sBc[tid] != 0.f) atomicAdd(&g_Bc[tid], sBc[tid]);
        }
    }
    gridBar(NB);

    // ---- phase 2: scatter exceptions into delta ----
    {
        const int cb5[5] = {0, 64, 192, 448, 960};
        for (int l = 0; l < 5; l++) {
            int n = min(g_excCnt[l], EXC_CAP);
            for (int j = gt; j < n; j += NTH) {
                unsigned e = g_exc[l * EXC_CAP + j];
                int p = e & 0x3FFFF;
                int c = (e >> 18) & 0x1FF;
                int g = (e >> 27) & 7;
                float d = g_ptab[cb5[l] + c][g] - g_ptab[cb5[l] + c][5];
                atomicAdd(&g_delta[pOff[l] + p], d);
            }
        }
    }
    gridBar(2 * NB);

    // ---- phase 3: proc min/max per layer (virtual 256-thread units) ----
    {
        const int bLo[6] = {0, 900, 1125, 1182, 1197, 1201};
        for (int u = blockIdx.x; u < 1201; u += NB) {
            int layer = 0;
            #pragma unroll
            for (int l = 1; l < 5; l++) if (u >= bLo[l]) layer = l;
            int i = (u - bLo[layer]) * 256 + tid;
            float mn = INFINITY, mx = -INFINITY;
            if (i < HWs[layer]) {
                int W = Hs[layer];
                int y = i / W, x = i - y * W;
                bool border = (y == 0 || x == 0 || y == W - 1 || x == W - 1);
                float v = border ? g_Bc[layer] : (g_S5[layer] + g_delta[pOff[layer] + i]);
                mn = v; mx = v;
            }
            blockMinMax(mn, mx);
            if (tid == 0) {
                atomicMin(&g_procmin[layer], fkey(mn));
                atomicMax(&g_procmax[layer], fkey(mx));
            }
        }
    }
    gridBar(3 * NB);

    // ---- phase 4: resize (jax linear antialias) + layer stats ----
    {
        __shared__ unsigned srmn[5], srmx[5];
        __shared__ float srsm[5];
        if (tid < 5) { srmn[tid] = 0xFFFFFFFFu; srmx[tid] = 0u; srsm[tid] = 0.f; }
        __syncthreads();
        for (int o = gt; o < 288000; o += NTH) {
            int layer = o / 57600;
            int oo = o - layer * 57600;
            int H = Hs[layer], W = H;
            float pmn = funkey(g_procmin[layer]);
            float pmx = funkey(g_procmax[layer]);
            float prng = pmx - pmn;
            float S5 = g_S5[layer], Bc = g_Bc[layer];
            int oy = oo / 240, ox = oo - oy * 240;
            float inv = (float)H / 240.0f;
            float ks = fmaxf(inv, 1.0f);
            float fy = ((float)oy + 0.5f) * inv - 0.5f;
            float fx = ((float)ox + 0.5f) * inv - 0.5f;
            int ylo = max(0, (int)ceilf(fy - ks)), yhi = min(H - 1, (int)floorf(fy + ks));
            int xlo = max(0, (int)ceilf(fx - ks)), xhi = min(W - 1, (int)floorf(fx + ks));
            float wx[8]; float wxs = 0.f;
            for (int j = xlo; j <= xhi; j++) {
                float w = fmaxf(0.f, 1.0f - fabsf(fx - (float)j) / ks);
                wx[j - xlo] = w; wxs += w;
            }
            const float* dl = g_delta + pOff[layer];
            float acc = 0.f, wys = 0.f;
            for (int j = ylo; j <= yhi; j++) {
                float wy = fmaxf(0.f, 1.0f - fabsf(fy - (float)j) / ks);
                wys += wy;
                if (wy != 0.f) {
                    bool rowB = (j == 0 || j == H - 1);
                    float rowacc = 0.f;
                    for (int i = xlo; i <= xhi; i++) {
                        bool border = rowB || i == 0 || i == W - 1;
                        float v = border ? Bc : (S5 + dl[j * W + i]);
                        float n = (prng == 0.f) ? 0.f : (v - pmn) / prng;
                        if (n < 0.2f) n = 0.f;
                        rowacc += wx[i - xlo] * n;
                    }
                    acc += wy * rowacc;
                }
            }
            float val = acc / (wys * wxs);
            g_resized[o] = val;
            // warp-level stat reduction (layer uniform across warp except at
            // 57600-boundaries; lanes are o-consecutive, bases 32-aligned)
            int base0 = o - lane;
            bool uni = (base0 / 57600) == ((base0 + 31) / 57600);
            if (uni) {
                float mnv = wrMin(val), mxv = wrMax(val), smv = wrSum(val);
                if (lane == 0) {
                    atomicMin(&srmn[layer], fkey(mnv));
                    atomicMax(&srmx[layer], fkey(mxv));
                    atomicAdd(&srsm[layer], smv);
                }
            } else {
                atomicMin(&srmn[layer], fkey(val));
                atomicMax(&srmx[layer], fkey(val));
                atomicAdd(&srsm[layer], val);
            }
        }
        __syncthreads();
        if (tid < 5) {
            if (srmn[tid] != 0xFFFFFFFFu) atomicMin(&g_rmin[tid], srmn[tid]);
            if (srmx[tid] != 0u)          atomicMax(&g_rmax[tid], srmx[tid]);
            if (srsm[tid] != 0.f)         atomicAdd(&g_rsum[tid], srsm[tid]);
        }
    }
    gridBar(4 * NB);

    // ---- phase 5: final fuse + output ----
    for (int o = gt; o < 57600; o += NTH) {
        float s = 0.f;
        float grp[5];
        #pragma unroll
        for (int l = 0; l < 5; l++) {
            float rmn = funkey(g_rmin[l]), rmx = funkey(g_rmax[l]);
            float rng = rmx - rmn;
            float mean = g_rsum[l] / 57600.0f;
            float w = (rmx - mean); w *= w;
            float v = g_resized[l * 57600 + o];
            float n = (rng == 0.f) ? 0.f : (v - rmn) / rng;
            float g = (w == 0.f || rng == 0.f) ? 0.f : (n * 256.0f);
            grp[l] = g;
            s += g;
        }
        out[o] = s;
        if (out_size >= 345600) {
            float* og = out + 57600;
            #pragma unroll
            for (int l = 0; l < 5; l++) og[o * 5 + l] = grp[l];
        }
    }
}

// ---------------- launch ----------------
extern "C" void kernel_launch(void* const* d_in, const int* in_sizes, int n_in,
                              void* d_out, int out_size) {
    const float* l0 = (const float*)d_in[0];
    const float* l1 = (const float*)d_in[1];
    const float* l2 = (const float*)d_in[2];
    const float* l3 = (const float*)d_in[3];
    const float* l4 = (const float*)d_in[4];

    k_minmaxAll<<<2816, 256>>>(l0, l1, l2, l3, l4);
    k_histAll<<<2816, 256>>>(l0, l1, l2, l3, l4);
    k_tail<<<NB, 256>>>((float*)d_out, out_size);
}